// round 11
// baseline (speedup 1.0000x reference)
#include <cuda_runtime.h>
#include <math.h>

#define MAX_IN 64
#define D_MODEL 64
#define ROWS_PER_BLOCK 16
#define THREADS 256
#define CAP 1024                 // rows per bucket
#define BUCKETS 64
#define BPB (CAP / ROWS_PER_BLOCK)          // 64 blocks per bucket
#define BUCKET_GRID (BUCKETS * BPB)         // 4096
#define MAXN (1 << 17)

__device__ int g_bucket[BUCKETS * CAP];
__device__ int g_meta[BUCKETS + 2];   // [1..64] = per-length counts, [65] = overflow count
__device__ int g_overflow[MAXN];

__device__ __forceinline__ float fast_tanh(float x) {
    float y;
    asm("tanh.approx.f32 %0, %1;" : "=f"(y) : "f"(x));
    return y;
}

__device__ __forceinline__ float gelu_tanh(float v) {
    const float c = 0.7978845608028654f;
    float u = c * (v + 0.044715f * v * v * v);
    return 0.5f * v * (1.0f + fast_tanh(u));
}

// ---------- prepass: fused hist + range-reserve + scatter (counters zeroed by memset node) ----------
__global__ void k_scatter(const int* __restrict__ lengths, int n) {
    __shared__ int h[BUCKETS + 1];
    __shared__ int bbase[BUCKETS + 1];
    int tid = threadIdx.x;
    if (tid <= BUCKETS) h[tid] = 0;
    __syncthreads();
    int r = blockIdx.x * blockDim.x + tid;
    int len = 0, rank = 0;
    if (r < n) {
        len = lengths[r];
        len = max(1, min(64, len));
        rank = atomicAdd(&h[len], 1);
    }
    __syncthreads();
    if (tid <= BUCKETS && h[tid] > 0) bbase[tid] = atomicAdd(&g_meta[tid], h[tid]);
    __syncthreads();
    if (r < n) {
        int pos = bbase[len] + rank;
        if (pos < CAP) {
            g_bucket[(len - 1) * CAP + pos] = r;
        } else {
            int o = atomicAdd(&g_meta[BUCKETS + 1], 1);
            g_overflow[o] = r;
        }
    }
}

// ---------- main kernel: length-homogeneous blocks, exact-length loop ----------
__global__ __launch_bounds__(THREADS, 6)
void fe_kernel(const float* __restrict__ seg,
               const float* __restrict__ W,
               const float* __restrict__ b,
               const int*   __restrict__ lengths,
               float* __restrict__ out,
               int n)
{
    __shared__ float sx[ROWS_PER_BLOCK][MAX_IN];
    __shared__ int   slen[ROWS_PER_BLOCK];
    __shared__ int   sidx[ROWS_PER_BLOCK];

    const int tid = threadIdx.x;

    if (blockIdx.x < BUCKET_GRID) {
        // bucket blocks: bucket 0 = len 64 (longest first -> clean tail wave)
        int bucket = blockIdx.x >> 6;
        int slot   = blockIdx.x & 63;
        int len    = BUCKETS - bucket;
        int cnt    = min(g_meta[len], CAP);
        int start  = slot * ROWS_PER_BLOCK;
        if (start >= cnt) return;
        if (tid < ROWS_PER_BLOCK) {
            int r = start + tid;
            if (r < cnt) {
                sidx[tid] = g_bucket[(len - 1) * CAP + r];
                slen[tid] = len;
            } else {
                sidx[tid] = 0;
                slen[tid] = 0;
            }
        }
    } else {
        // overflow blocks (normally all-empty)
        int j = blockIdx.x - BUCKET_GRID;
        int cnt = g_meta[BUCKETS + 1];
        int start = j * ROWS_PER_BLOCK;
        if (start >= cnt) return;
        if (tid < ROWS_PER_BLOCK) {
            int r = start + tid;
            if (r < cnt) {
                int src = g_overflow[r];
                sidx[tid] = src;
                slen[tid] = lengths[src];
            } else {
                sidx[tid] = 0;
                slen[tid] = 0;
            }
        }
    }
    __syncthreads();

    // Cooperative unmasked copy of x rows into smem (exact-length loop never
    // reads beyond len, so masking is unnecessary)
    {
        int r  = tid >> 4;
        int c4 = tid & 15;
        float4 v = make_float4(0.f, 0.f, 0.f, 0.f);
        if (slen[r] > 0) {
            v = reinterpret_cast<const float4*>(seg)[(size_t)sidx[r] * 16 + c4];
        }
        *reinterpret_cast<float4*>(&sx[r][c4 * 4]) = v;
    }
    __syncthreads();

    const int g = tid >> 4;
    const int t = tid & 15;
    const int len = slen[g];
    if (len == 0) return;
    const int src = sidx[g];

    const float4* Wr = reinterpret_cast<const float4*>(W) + (size_t)src * 1024 + t;
    const float* xr = sx[g];

    float4 acc = make_float4(0.f, 0.f, 0.f, 0.f);

    const int len4 = len & ~3;
    int i = 0;
    #pragma unroll 1
    for (; i < len4; i += 4) {
        float4 w0 = Wr[(i + 0) * 16];
        float4 w1 = Wr[(i + 1) * 16];
        float4 w2 = Wr[(i + 2) * 16];
        float4 w3 = Wr[(i + 3) * 16];
        float4 xv = *reinterpret_cast<const float4*>(xr + i);
        acc.x += xv.x * w0.x + xv.y * w1.x + xv.z * w2.x + xv.w * w3.x;
        acc.y += xv.x * w0.y + xv.y * w1.y + xv.z * w2.y + xv.w * w3.y;
        acc.z += xv.x * w0.z + xv.y * w1.z + xv.z * w2.z + xv.w * w3.z;
        acc.w += xv.x * w0.w + xv.y * w1.w + xv.z * w2.w + xv.w * w3.w;
    }
    // exact-length tail (0-3 iterations, identical across the whole block)
    for (; i < len; i++) {
        float4 w = Wr[i * 16];
        float xv = xr[i];
        acc.x += xv * w.x;
        acc.y += xv * w.y;
        acc.z += xv * w.z;
        acc.w += xv * w.w;
    }

    float4 bb = reinterpret_cast<const float4*>(b)[(size_t)src * 16 + t];
    float4 r4;
    r4.x = gelu_tanh(acc.x + bb.x);
    r4.y = gelu_tanh(acc.y + bb.y);
    r4.z = gelu_tanh(acc.z + bb.z);
    r4.w = gelu_tanh(acc.w + bb.w);

    reinterpret_cast<float4*>(out)[(size_t)src * 16 + t] = r4;
}

// ---------- fallback for n > MAXN (defensive; not hit at N=50000) ----------
__global__ __launch_bounds__(THREADS, 6)
void fe_plain(const float* __restrict__ seg,
              const float* __restrict__ W,
              const float* __restrict__ b,
              const int*   __restrict__ lengths,
              float* __restrict__ out,
              int n)
{
    __shared__ float sx[ROWS_PER_BLOCK][MAX_IN];
    __shared__ int   slen[ROWS_PER_BLOCK];

    const int row0 = blockIdx.x * ROWS_PER_BLOCK;
    const int tid  = threadIdx.x;

    if (tid < ROWS_PER_BLOCK) {
        int r = row0 + tid;
        slen[tid] = (r < n) ? lengths[r] : 0;
    }
    __syncthreads();
    {
        int r  = tid >> 4;
        int c4 = tid & 15;
        float4 v = make_float4(0.f, 0.f, 0.f, 0.f);
        if (slen[r] > 0)
            v = reinterpret_cast<const float4*>(seg)[(size_t)(row0 + r) * 16 + c4];
        *reinterpret_cast<float4*>(&sx[r][c4 * 4]) = v;
    }
    __syncthreads();

    const int g = tid >> 4;
    const int t = tid & 15;
    const int row = row0 + g;
    if (row >= n) return;
    const int len = slen[g];

    const float4* Wr = reinterpret_cast<const float4*>(W) + (size_t)row * 1024 + t;
    const float* xr = sx[g];
    float4 acc = make_float4(0.f, 0.f, 0.f, 0.f);

    const int len4 = len & ~3;
    int i = 0;
    #pragma unroll 1
    for (; i < len4; i += 4) {
        float4 w0 = Wr[(i + 0) * 16];
        float4 w1 = Wr[(i + 1) * 16];
        float4 w2 = Wr[(i + 2) * 16];
        float4 w3 = Wr[(i + 3) * 16];
        float4 xv = *reinterpret_cast<const float4*>(xr + i);
        acc.x += xv.x * w0.x + xv.y * w1.x + xv.z * w2.x + xv.w * w3.x;
        acc.y += xv.x * w0.y + xv.y * w1.y + xv.z * w2.y + xv.w * w3.y;
        acc.z += xv.x * w0.z + xv.y * w1.z + xv.z * w2.z + xv.w * w3.z;
        acc.w += xv.x * w0.w + xv.y * w1.w + xv.z * w2.w + xv.w * w3.w;
    }
    for (; i < len; i++) {
        float4 w = Wr[i * 16];
        float xv = xr[i];
        acc.x += xv * w.x; acc.y += xv * w.y; acc.z += xv * w.z; acc.w += xv * w.w;
    }

    float4 bb = reinterpret_cast<const float4*>(b)[(size_t)row * 16 + t];
    float4 r4;
    r4.x = gelu_tanh(acc.x + bb.x);
    r4.y = gelu_tanh(acc.y + bb.y);
    r4.z = gelu_tanh(acc.z + bb.z);
    r4.w = gelu_tanh(acc.w + bb.w);
    reinterpret_cast<float4*>(out)[(size_t)row * 16 + t] = r4;
}

extern "C" void kernel_launch(void* const* d_in, const int* in_sizes, int n_in,
                              void* d_out, int out_size) {
    const float* seg     = (const float*)d_in[0];
    const float* W       = (const float*)d_in[1];
    const float* b       = (const float*)d_in[2];
    const int*   lengths = (const int*)d_in[3];
    float* out = (float*)d_out;

    int n = in_sizes[3];

    if (n <= MAXN) {
        void* meta_ptr = nullptr;
        cudaGetSymbolAddress(&meta_ptr, g_meta);
        // Graph-capturable memset node: zero counters (no kernel launch cost)
        cudaMemsetAsync(meta_ptr, 0, sizeof(int) * (BUCKETS + 2));

        int sgrid    = (n + THREADS - 1) / THREADS;
        int ovf_grid = (n + ROWS_PER_BLOCK - 1) / ROWS_PER_BLOCK;

        k_scatter<<<sgrid, THREADS>>>(lengths, n);
        fe_kernel<<<BUCKET_GRID + ovf_grid, THREADS>>>(seg, W, b, lengths, out, n);
    } else {
        int grid = (n + ROWS_PER_BLOCK - 1) / ROWS_PER_BLOCK;
        fe_plain<<<grid, THREADS>>>(seg, W, b, lengths, out, n);
    }
}